// round 4
// baseline (speedup 1.0000x reference)
#include <cuda_runtime.h>

#define Bn 64
#define Tn 512
#define Cn 256
#define NC 8            // num_clusters: reference computes min(8, T) = 8, fixed
#define INFV 1e9f

static __device__ float g_XN[(size_t)Bn * Tn * Cn];   // 32 MB normalized x
static __device__ float g_D [(size_t)Bn * Tn * Tn];   // 64 MB distance matrices

// ---------------------------------------------------------------------------
// Kernel 1: row-normalize x  (xn = x / (||x|| + 1e-8)), one warp per row
// ---------------------------------------------------------------------------
__global__ void knorm_kernel(const float* __restrict__ x) {
    int row  = blockIdx.x * 8 + (threadIdx.x >> 5);
    int lane = threadIdx.x & 31;
    const float* xr = x + (size_t)row * Cn;
    float s = 0.f;
    #pragma unroll
    for (int c = lane; c < Cn; c += 32) { float v = xr[c]; s = fmaf(v, v, s); }
    #pragma unroll
    for (int o = 16; o; o >>= 1) s += __shfl_xor_sync(0xffffffffu, s, o);
    float denom = sqrtf(s) + 1e-8f;
    float* xo = g_XN + (size_t)row * Cn;
    #pragma unroll
    for (int c = lane; c < Cn; c += 32) xo[c] = xr[c] / denom;
}

// ---------------------------------------------------------------------------
// Kernel 2: Gram / distance matrix  D = 1 - XN @ XN^T, diag = INF
// 64x64 tile per CTA, 256 threads, 4x4 micro-tile, K-step 16
// ---------------------------------------------------------------------------
__global__ void kgram_kernel() {
    __shared__ float As[64][17];
    __shared__ float Bs[64][17];
    const int b  = blockIdx.z;
    const int i0 = blockIdx.y * 64;
    const int j0 = blockIdx.x * 64;
    const int tid = threadIdx.x;
    const int tx = tid & 15, ty = tid >> 4;
    const int lrow = tid >> 2;
    const int lc4  = (tid & 3) << 2;
    const float* XA = g_XN + ((size_t)b * Tn + i0) * Cn;
    const float* XB = g_XN + ((size_t)b * Tn + j0) * Cn;
    float acc[4][4] = {};
    for (int k0 = 0; k0 < Cn; k0 += 16) {
        float4 a4 = *(const float4*)(XA + (size_t)lrow * Cn + k0 + lc4);
        float4 b4 = *(const float4*)(XB + (size_t)lrow * Cn + k0 + lc4);
        As[lrow][lc4+0] = a4.x; As[lrow][lc4+1] = a4.y;
        As[lrow][lc4+2] = a4.z; As[lrow][lc4+3] = a4.w;
        Bs[lrow][lc4+0] = b4.x; Bs[lrow][lc4+1] = b4.y;
        Bs[lrow][lc4+2] = b4.z; Bs[lrow][lc4+3] = b4.w;
        __syncthreads();
        #pragma unroll
        for (int kk = 0; kk < 16; kk++) {
            float a[4], bb[4];
            #pragma unroll
            for (int r = 0; r < 4; r++) { a[r] = As[ty*4+r][kk]; bb[r] = Bs[tx*4+r][kk]; }
            #pragma unroll
            for (int r = 0; r < 4; r++)
                #pragma unroll
                for (int c = 0; c < 4; c++)
                    acc[r][c] = fmaf(a[r], bb[c], acc[r][c]);
        }
        __syncthreads();
    }
    #pragma unroll
    for (int r = 0; r < 4; r++) {
        int gi = i0 + ty*4 + r;
        float* drow = g_D + ((size_t)b * Tn + gi) * Tn;
        #pragma unroll
        for (int c = 0; c < 4; c++) {
            int gj = j0 + tx*4 + c;
            drow[gj] = (gi == gj) ? INFV : (1.0f - acc[r][c]);
        }
    }
}

// ---------------------------------------------------------------------------
// Kernel 3: sequential agglomerative merges + relabel, one CTA per batch
// Per-row NN cache in SMEM; ties broken lexicographically on (val, row, col)
// to replicate jnp.argmin's first-flat-index semantics.
// Output written as FLOAT32 (harness __output__ dtype).
// ---------------------------------------------------------------------------
__device__ __forceinline__ void pairmin(float& v, int& i, float ov, int oi) {
    if (ov < v || (ov == v && oi < i)) { v = ov; i = oi; }
}

__global__ void __launch_bounds__(512) kmerge_kernel(float* __restrict__ out) {
    const int b = blockIdx.x;
    const int t = threadIdx.x;
    const int lane = t & 31, warp = t >> 5;
    float* D = g_D + (size_t)b * Tn * Tn;

    __shared__ float minval[Tn];
    __shared__ int   minidx[Tn];
    __shared__ float sizes[Tn];
    __shared__ int   assign[Tn];
    __shared__ int   rlist[Tn];
    __shared__ int   cnt;
    __shared__ int   sbi, sbj;
    __shared__ float wv[16];
    __shared__ int   wr[16];

    sizes[t]  = 1.0f;
    assign[t] = t;
    __syncthreads();

    // initial per-row (min value, min col) — warp w handles rows w, w+16, ...
    for (int r = warp; r < Tn; r += 16) {
        const float* row = D + (size_t)r * Tn;
        float v = 3.402823e38f; int idx = 0;
        for (int c = lane; c < Tn; c += 32) {
            float d = row[c];
            if (d < v) { v = d; idx = c; }
        }
        #pragma unroll
        for (int o = 16; o; o >>= 1) {
            float ov = __shfl_xor_sync(0xffffffffu, v, o);
            int   oi = __shfl_xor_sync(0xffffffffu, idx, o);
            pairmin(v, idx, ov, oi);
        }
        if (lane == 0) { minval[r] = v; minidx[r] = idx; }
    }
    __syncthreads();

    const int nm = Tn - NC;   // 504 merges

    for (int m = 0; m < nm; ++m) {
        // ---- global argmin over cached per-row minima (tie: smaller row) ----
        float v = minval[t]; int r = t;
        #pragma unroll
        for (int o = 16; o; o >>= 1) {
            float ov = __shfl_xor_sync(0xffffffffu, v, o);
            int  orr = __shfl_xor_sync(0xffffffffu, r, o);
            pairmin(v, r, ov, orr);
        }
        if (lane == 0) { wv[warp] = v; wr[warp] = r; }
        __syncthreads();
        if (warp == 0) {
            float v2 = (lane < 16) ? wv[lane] : 3.402823e38f;
            int   r2 = (lane < 16) ? wr[lane] : 0;
            #pragma unroll
            for (int o = 8; o; o >>= 1) {
                float ov = __shfl_xor_sync(0xffffffffu, v2, o);
                int  orr = __shfl_xor_sync(0xffffffffu, r2, o);
                pairmin(v2, r2, ov, orr);
            }
            if (lane == 0) {
                int c = minidx[r2];
                sbi = min(r2, c);
                sbj = max(r2, c);
            }
        }
        if (t == 256) cnt = 0;
        __syncthreads();

        const int i = sbi, j = sbj;
        const float ni  = sizes[i], nj = sizes[j];
        const float szk = sizes[t];
        __syncthreads();   // separate sizes reads from sizes writes below

        // ---- merged row: average linkage (exact non-fused op order) ----
        float a  = D[(size_t)i * Tn + t];
        float dj = D[(size_t)j * Tn + t];
        float nr = __fdiv_rn(__fadd_rn(__fmul_rn(ni, a), __fmul_rn(nj, dj)),
                             __fadd_rn(ni, nj));
        if (t == i || t == j) nr = INFV;
        D[(size_t)i * Tn + t] = nr;
        D[(size_t)t * Tn + i] = nr;
        D[(size_t)j * Tn + t] = INFV;
        D[(size_t)t * Tn + j] = INFV;

        // ---- incremental NN-cache maintenance ----
        if (t == i) {
            rlist[atomicAdd(&cnt, 1)] = i;   // merged row: full recompute
            sizes[i] = ni + nj;
        } else if (t == j) {
            minval[t] = 1e30f;               // dead row never wins argmin
            sizes[j]  = 0.0f;
        } else if (szk > 0.0f) {
            int mi = minidx[t];
            if (mi == i || mi == j) {
                rlist[atomicAdd(&cnt, 1)] = t;   // cached NN invalidated
            } else if (nr < minval[t] || (nr == minval[t] && i < mi)) {
                minval[t] = nr; minidx[t] = i;
            }
        }
        if (assign[t] == j) assign[t] = i;
        __syncthreads();   // D writes + rlist visible

        // ---- full-row re-reductions, one warp per row, 16 rows per pass ----
        const int c_ = cnt;
        for (int base = 0; base < c_; base += 16) {
            int li = base + warp;
            if (li < c_) {
                int rr = rlist[li];
                const float* row = D + (size_t)rr * Tn;
                float rv = 3.402823e38f; int ridx = 0;
                for (int c = lane; c < Tn; c += 32) {
                    float d = row[c];
                    if (d < rv) { rv = d; ridx = c; }
                }
                #pragma unroll
                for (int o = 16; o; o >>= 1) {
                    float ov = __shfl_xor_sync(0xffffffffu, rv, o);
                    int   oi = __shfl_xor_sync(0xffffffffu, ridx, o);
                    pairmin(rv, ridx, ov, oi);
                }
                if (lane == 0) { minval[rr] = rv; minidx[rr] = ridx; }
            }
        }
        __syncthreads();
    }

    // ---- canonical relabel: rank clusters by first token occurrence ----
    rlist[t] = (assign[t] == t) ? 1 : 0;
    __syncthreads();
    for (int off = 1; off < Tn; off <<= 1) {
        int add = (t >= off) ? rlist[t - off] : 0;
        __syncthreads();
        rlist[t] += add;
        __syncthreads();
    }
    // write as float32 — harness output dtype
    out[(size_t)b * Tn + t] = (float)(rlist[assign[t]] - 1);
}

// ---------------------------------------------------------------------------
extern "C" void kernel_launch(void* const* d_in, const int* in_sizes, int n_in,
                              void* d_out, int out_size) {
    // x = the big float tensor (8.4M elements); default to d_in[0].
    const float* x = (const float*)d_in[0];
    for (int k = 0; k < n_in; k++)
        if (in_sizes[k] >= Bn * Tn * Cn) { x = (const float*)d_in[k]; break; }
    float* out = (float*)d_out;

    knorm_kernel<<<(Bn * Tn) / 8, 256>>>(x);
    dim3 gg(Tn / 64, Tn / 64, Bn);
    kgram_kernel<<<gg, 256>>>();
    kmerge_kernel<<<Bn, Tn>>>(out);
}

// round 5
// speedup vs baseline: 1.2693x; 1.2693x over previous
#include <cuda_runtime.h>

#define Bn 64
#define Tn 512
#define Cn 256
#define NC 8            // num_clusters: reference computes min(8, T) = 8, fixed
#define INFV 1e9f

typedef unsigned long long ull;

static __device__ float g_XN[(size_t)Bn * Tn * Cn];   // 32 MB normalized x
static __device__ float g_D [(size_t)Bn * Tn * Tn];   // 64 MB distance matrices

// ---------------------------------------------------------------------------
// monotone (value, index) packing: u64 compare == lexicographic (val, idx)
// ---------------------------------------------------------------------------
__device__ __forceinline__ ull dpack(float v, unsigned c) {
    unsigned u = __float_as_uint(v);
    u ^= ((unsigned)(((int)u) >> 31)) | 0x80000000u;   // order-preserving map
    return ((ull)u << 32) | c;
}
__device__ __forceinline__ void kmin(ull& k, ull o) { if (o < k) k = o; }

// ---------------------------------------------------------------------------
// Kernel 1: row-normalize x  (xn = x / (||x|| + 1e-8)), one warp per row
// ---------------------------------------------------------------------------
__global__ void knorm_kernel(const float* __restrict__ x) {
    int row  = blockIdx.x * 8 + (threadIdx.x >> 5);
    int lane = threadIdx.x & 31;
    const float* xr = x + (size_t)row * Cn;
    float s = 0.f;
    #pragma unroll
    for (int c = lane; c < Cn; c += 32) { float v = xr[c]; s = fmaf(v, v, s); }
    #pragma unroll
    for (int o = 16; o; o >>= 1) s += __shfl_xor_sync(0xffffffffu, s, o);
    float denom = sqrtf(s) + 1e-8f;
    float* xo = g_XN + (size_t)row * Cn;
    #pragma unroll
    for (int c = lane; c < Cn; c += 32) xo[c] = xr[c] / denom;
}

// ---------------------------------------------------------------------------
// Kernel 2: D = 1 - XN @ XN^T, diag = INF.  128x128 tile, 256 thr, 8x8 micro
// k-major SMEM so fragments load as LDS.128 (FMA-bound, not LDS-bound)
// ---------------------------------------------------------------------------
__global__ void __launch_bounds__(256, 2) kgram_kernel() {
    __shared__ float As[16][128];
    __shared__ float Bs[16][128];
    const int b  = blockIdx.z;
    const int i0 = blockIdx.y * 128;
    const int j0 = blockIdx.x * 128;
    const int tid = threadIdx.x;
    const int tx = tid & 15, ty = tid >> 4;
    const float* XA = g_XN + ((size_t)b * Tn + i0) * Cn;
    const float* XB = g_XN + ((size_t)b * Tn + j0) * Cn;
    float acc[8][8] = {};
    for (int k0 = 0; k0 < Cn; k0 += 16) {
        #pragma unroll
        for (int q = 0; q < 2; q++) {
            int f   = tid + q * 256;        // 512 float4 slots per matrix
            int row = f >> 2;
            int k4  = (f & 3) << 2;
            float4 a4 = *(const float4*)(XA + (size_t)row * Cn + k0 + k4);
            float4 b4 = *(const float4*)(XB + (size_t)row * Cn + k0 + k4);
            As[k4+0][row] = a4.x; As[k4+1][row] = a4.y;
            As[k4+2][row] = a4.z; As[k4+3][row] = a4.w;
            Bs[k4+0][row] = b4.x; Bs[k4+1][row] = b4.y;
            Bs[k4+2][row] = b4.z; Bs[k4+3][row] = b4.w;
        }
        __syncthreads();
        #pragma unroll
        for (int kk = 0; kk < 16; kk++) {
            float a[8], bb[8];
            *(float4*)&a[0]  = *(const float4*)&As[kk][ty * 8];
            *(float4*)&a[4]  = *(const float4*)&As[kk][ty * 8 + 4];
            *(float4*)&bb[0] = *(const float4*)&Bs[kk][tx * 8];
            *(float4*)&bb[4] = *(const float4*)&Bs[kk][tx * 8 + 4];
            #pragma unroll
            for (int r = 0; r < 8; r++)
                #pragma unroll
                for (int c = 0; c < 8; c++)
                    acc[r][c] = fmaf(a[r], bb[c], acc[r][c]);
        }
        __syncthreads();
    }
    #pragma unroll
    for (int r = 0; r < 8; r++) {
        int gi = i0 + ty * 8 + r;
        float* drow = g_D + ((size_t)b * Tn + gi) * Tn + j0 + tx * 8;
        float o[8];
        #pragma unroll
        for (int c = 0; c < 8; c++) {
            int gj = j0 + tx * 8 + c;
            o[c] = (gi == gj) ? INFV : (1.0f - acc[r][c]);
        }
        *(float4*)drow       = *(float4*)&o[0];
        *(float4*)(drow + 4) = *(float4*)&o[4];
    }
}

// ---------------------------------------------------------------------------
// Kernel 3: sequential agglomerative merges + relabel, one CTA per batch.
// 3 barriers/merge. Packed-u64 NN cache; alive bitmask replaces INF writes
// for dead rows/cols; warp0-only global argmin; float4 row scans.
// ---------------------------------------------------------------------------
__global__ void __launch_bounds__(512) kmerge_kernel(float* __restrict__ out) {
    const int b = blockIdx.x;
    const int t = threadIdx.x;
    const int lane = t & 31, warp = t >> 5;
    float* D = g_D + (size_t)b * Tn * Tn;

    __shared__ ull      minkey[Tn];       // (monotone val, min col) per row
    __shared__ float    sizes[Tn];        // touched only by warp0 lane0
    __shared__ int      assign[Tn];
    __shared__ int      rlist[Tn];
    __shared__ unsigned alivem[Tn / 32];
    __shared__ int      cnt;
    __shared__ int      si, sj;
    __shared__ float    sni, snj;

    sizes[t]  = 1.0f;
    assign[t] = t;
    if (t < Tn / 32) alivem[t] = 0xffffffffu;
    __syncthreads();

    // initial per-row scans (all columns alive; diag already INF)
    for (int r = warp; r < Tn; r += 16) {
        const float4* rowv = (const float4*)(D + (size_t)r * Tn);
        ull k = ~0ull;
        for (int c4 = lane; c4 < Tn / 4; c4 += 32) {
            float4 v = rowv[c4];
            unsigned c = c4 * 4;
            kmin(k, dpack(v.x, c));   kmin(k, dpack(v.y, c + 1));
            kmin(k, dpack(v.z, c + 2)); kmin(k, dpack(v.w, c + 3));
        }
        #pragma unroll
        for (int o = 16; o; o >>= 1) kmin(k, __shfl_xor_sync(0xffffffffu, k, o));
        if (lane == 0) minkey[r] = k;
    }
    __syncthreads();

    for (int m = 0; m < Tn - NC; ++m) {
        // ---- warp0: global argmin over cached keys, tie (val, row, col) ----
        if (warp == 0) {
            ull gk = ~0ull;
            const ull* mk = minkey + lane * 16;
            #pragma unroll
            for (int q = 0; q < 16; q++) {
                ull rk = (mk[q] & 0xFFFFFFFF00000000ull) | (unsigned)(lane * 16 + q);
                kmin(gk, rk);
            }
            #pragma unroll
            for (int o = 16; o; o >>= 1) kmin(gk, __shfl_xor_sync(0xffffffffu, gk, o));
            if (lane == 0) {
                int r = (int)(unsigned)gk;
                int c = (int)(unsigned)minkey[r];
                int i = min(r, c), j = max(r, c);
                si = i; sj = j;
                sni = sizes[i]; snj = sizes[j];
                sizes[i] = sizes[i] + sizes[j];   // only lane0 ever touches sizes
                sizes[j] = 0.0f;
                alivem[j >> 5] &= ~(1u << (j & 31));
                minkey[j] = ~0ull;
                rlist[0] = i; cnt = 1;            // merged row always rescanned
            }
        }
        __syncthreads();

        const int   i = si, j = sj;
        const float ni = sni, nj = snj;
        const bool  isalive = (alivem[t >> 5] >> (t & 31)) & 1u;

        if (isalive) {
            // merged row value at col t: exact non-fused reference op order
            float a  = D[(size_t)i * Tn + t];
            float dj = D[(size_t)j * Tn + t];
            float nr = __fdiv_rn(__fadd_rn(__fmul_rn(ni, a), __fmul_rn(nj, dj)),
                                 __fadd_rn(ni, nj));
            if (t == i) nr = INFV;
            D[(size_t)i * Tn + t] = nr;   // row i (coalesced over alive t)
            D[(size_t)t * Tn + i] = nr;   // col i (scattered, alive rows only)
            if (t != i) {
                ull key = minkey[t];
                int mc  = (int)(unsigned)key;
                if (mc == i || mc == j) {
                    rlist[atomicAdd(&cnt, 1)] = t;          // cached NN died
                } else {
                    ull cand = dpack(nr, (unsigned)i);
                    if (cand < key) minkey[t] = cand;
                }
            }
        }
        if (assign[t] == j) assign[t] = i;
        __syncthreads();

        // ---- full-row re-reductions (masked, float4), one warp per row ----
        const int c_ = cnt;
        for (int li = warp; li < c_; li += 16) {
            int rr = rlist[li];
            const float4* rowv = (const float4*)(D + (size_t)rr * Tn);
            ull k = ~0ull;
            for (int c4 = lane; c4 < Tn / 4; c4 += 32) {
                unsigned mb = (alivem[c4 >> 3] >> ((c4 & 7) * 4)) & 0xFu;
                if (mb) {
                    float4 v = rowv[c4];
                    unsigned c = c4 * 4;
                    if (mb & 1u) kmin(k, dpack(v.x, c));
                    if (mb & 2u) kmin(k, dpack(v.y, c + 1));
                    if (mb & 4u) kmin(k, dpack(v.z, c + 2));
                    if (mb & 8u) kmin(k, dpack(v.w, c + 3));
                }
            }
            #pragma unroll
            for (int o = 16; o; o >>= 1) kmin(k, __shfl_xor_sync(0xffffffffu, k, o));
            if (lane == 0) minkey[rr] = k;
        }
        __syncthreads();
    }

    // ---- canonical relabel: rank clusters by first token occurrence ----
    rlist[t] = (assign[t] == t) ? 1 : 0;
    __syncthreads();
    for (int off = 1; off < Tn; off <<= 1) {
        int add = (t >= off) ? rlist[t - off] : 0;
        __syncthreads();
        rlist[t] += add;
        __syncthreads();
    }
    out[(size_t)b * Tn + t] = (float)(rlist[assign[t]] - 1);
}

// ---------------------------------------------------------------------------
extern "C" void kernel_launch(void* const* d_in, const int* in_sizes, int n_in,
                              void* d_out, int out_size) {
    const float* x = (const float*)d_in[0];
    for (int k = 0; k < n_in; k++)
        if (in_sizes[k] >= Bn * Tn * Cn) { x = (const float*)d_in[k]; break; }
    float* out = (float*)d_out;

    knorm_kernel<<<(Bn * Tn) / 8, 256>>>(x);
    dim3 gg(Tn / 128, Tn / 128, Bn);
    kgram_kernel<<<gg, 256>>>();
    kmerge_kernel<<<Bn, Tn>>>(out);
}